// round 7
// baseline (speedup 1.0000x reference)
#include <cuda_runtime.h>
#include <cstdint>

// BMM_S8T_S8N_S32T_WITH_SCALING: out[b,m,n] = round(alpha * sum_k A[b,m,k]*B[b,n,k])
// B=64, M=N=1024, K=128.
//
// HARNESS DTYPE FINDINGS (rounds 5-6):
//  - d_out is compared as FLOAT32  (int32 stores -> rel_err=nan on negatives)
//  - a, b are materialized as INT32 (values in [-128,127]); reading them as
//    int8 gave rel_err = sqrt(1.25) exactly (32-of-128 valid products,
//    uncorrelated) -- identical across two independent compute cores.
//
// So: load int32, pack low bytes -> int8 shared tiles, IMMA compute,
// store float32.

static constexpr int M_DIM = 1024;
static constexpr int N_DIM = 1024;
static constexpr int K_DIM = 128;
static constexpr float ALPHA_CONST = 0.0078125f;   // 2^-7, from setup_inputs

__device__ __forceinline__ uint32_t sw128(uint32_t off) {
    return off ^ ((off >> 3) & 0x70);
}

__device__ __forceinline__ uint32_t pack4(int4 w) {
    // low byte of each int32 -> one packed uint32 [b0,b1,b2,b3]
    uint32_t lo = __byte_perm((uint32_t)w.x, (uint32_t)w.y, 0x0040);
    uint32_t hi = __byte_perm((uint32_t)w.z, (uint32_t)w.w, 0x0040);
    return __byte_perm(lo, hi, 0x5410);
}

__global__ __launch_bounds__(256, 2)
void bmm_s8_imma_kernel(const int* __restrict__ A,
                        const int* __restrict__ B,
                        const float* __restrict__ alpha_p,
                        float* __restrict__ out)
{
    __shared__ int8_t sA[128 * 128];
    __shared__ int8_t sB[128 * 128];

    const int bz = blockIdx.z;          // batch
    const int bm = blockIdx.y;          // m tile
    const int bn = blockIdx.x;          // n tile
    const int tid = threadIdx.x;

    const float alpha = alpha_p ? *alpha_p : ALPHA_CONST;

    // Tile = 128 rows x 128 k-values; contiguous 64KB of int32 gmem each.
    const int4* gA4 = reinterpret_cast<const int4*>(
        A + ((size_t)bz * M_DIM + (size_t)bm * 128) * K_DIM);
    const int4* gB4 = reinterpret_cast<const int4*>(
        B + ((size_t)bz * N_DIM + (size_t)bn * 128) * K_DIM);

    // Cooperative load+pack: 1024 16B smem chunks per tile; each chunk is
    // built from 4 int4 gmem loads (16 int32 values -> 16 int8 bytes).
    #pragma unroll
    for (int i = 0; i < 4; i++) {
        int idx = tid + i * 256;              // smem 16B-chunk index
        int row = idx >> 3;                   // 8 chunks per 128B row
        int chunk = idx & 7;
        int g = row * 32 + chunk * 4;         // int4 index into gmem tile
        uint32_t soff = (uint32_t)row * 128 + (uint32_t)((chunk ^ (row & 7)) << 4);

        uint4 pa, pb;
        pa.x = pack4(gA4[g + 0]); pa.y = pack4(gA4[g + 1]);
        pa.z = pack4(gA4[g + 2]); pa.w = pack4(gA4[g + 3]);
        pb.x = pack4(gB4[g + 0]); pb.y = pack4(gB4[g + 1]);
        pb.z = pack4(gB4[g + 2]); pb.w = pack4(gB4[g + 3]);

        *reinterpret_cast<uint4*>(sA + soff) = pa;
        *reinterpret_cast<uint4*>(sB + soff) = pb;
    }
    __syncthreads();

    const int warp = tid >> 5;
    const int lane = tid & 31;
    const int mBase = (warp >> 2) * 64;   // warp row: 0 or 64
    const int nBase = (warp & 3) * 32;    // warp col: 0,32,64,96

    uint32_t aS = (uint32_t)__cvta_generic_to_shared(sA);
    uint32_t bS = (uint32_t)__cvta_generic_to_shared(sB);

    int acc[4][4][4];
    #pragma unroll
    for (int mi = 0; mi < 4; mi++)
        #pragma unroll
        for (int ni = 0; ni < 4; ni++)
            #pragma unroll
            for (int r = 0; r < 4; r++)
                acc[mi][ni][r] = 0;

    // ldmatrix x4 lane->matrix map matches m16n8k32.s8 fragment order.
    const int sub = lane >> 3;
    const int r8 = lane & 7;
    const int ld_row_off = ((sub & 1) << 3) + r8;   // row within 16-row group
    const int ld_col_off = (sub >> 1) << 4;         // 0 or 16 bytes

    #pragma unroll
    for (int kc = 0; kc < 4; kc++) {                // 4 x k32 steps
        const int kcol = kc * 32 + ld_col_off;

        uint32_t a[4][4];
        #pragma unroll
        for (int mi = 0; mi < 4; mi++) {
            int row = mBase + mi * 16 + ld_row_off;
            uint32_t addr = aS + sw128((uint32_t)row * 128 + kcol);
            asm volatile(
                "ldmatrix.sync.aligned.m8n8.x4.shared.b16 {%0,%1,%2,%3}, [%4];"
                : "=r"(a[mi][0]), "=r"(a[mi][1]), "=r"(a[mi][2]), "=r"(a[mi][3])
                : "r"(addr));
        }

        uint32_t b[2][4];                            // 2 x (n16 x k32)
        #pragma unroll
        for (int nj = 0; nj < 2; nj++) {
            int row = nBase + nj * 16 + ld_row_off;
            uint32_t addr = bS + sw128((uint32_t)row * 128 + kcol);
            asm volatile(
                "ldmatrix.sync.aligned.m8n8.x4.shared.b16 {%0,%1,%2,%3}, [%4];"
                : "=r"(b[nj][0]), "=r"(b[nj][1]), "=r"(b[nj][2]), "=r"(b[nj][3])
                : "r"(addr));
        }

        #pragma unroll
        for (int mi = 0; mi < 4; mi++) {
            #pragma unroll
            for (int ni = 0; ni < 4; ni++) {
                const int nj = ni >> 1;
                const int up = ni & 1;
                uint32_t b0 = b[nj][up];
                uint32_t b1 = b[nj][up + 2];
                asm volatile(
                    "mma.sync.aligned.m16n8k32.row.col.s32.s8.s8.s32 "
                    "{%0,%1,%2,%3}, {%4,%5,%6,%7}, {%8,%9}, {%0,%1,%2,%3};"
                    : "+r"(acc[mi][ni][0]), "+r"(acc[mi][ni][1]),
                      "+r"(acc[mi][ni][2]), "+r"(acc[mi][ni][3])
                    : "r"(a[mi][0]), "r"(a[mi][1]), "r"(a[mi][2]), "r"(a[mi][3]),
                      "r"(b0), "r"(b1));
            }
        }
    }

    // Epilogue: scale, round-half-even (rintf == jnp.round), store FLOAT32.
    float* gOut = out + ((size_t)bz * M_DIM + (size_t)bm * 128) * N_DIM
                      + (size_t)bn * 128;
    const int g = lane >> 2;       // row within 8-row group
    const int tq = lane & 3;       // column quad

    #pragma unroll
    for (int mi = 0; mi < 4; mi++) {
        #pragma unroll
        for (int ni = 0; ni < 4; ni++) {
            int r0 = mBase + mi * 16 + g;
            int c  = nBase + ni * 8 + tq * 2;
            float2 v0, v1;
            v0.x = rintf((float)acc[mi][ni][0] * alpha);
            v0.y = rintf((float)acc[mi][ni][1] * alpha);
            v1.x = rintf((float)acc[mi][ni][2] * alpha);
            v1.y = rintf((float)acc[mi][ni][3] * alpha);
            *reinterpret_cast<float2*>(gOut + (size_t)r0 * N_DIM + c)       = v0;
            *reinterpret_cast<float2*>(gOut + (size_t)(r0 + 8) * N_DIM + c) = v1;
        }
    }
}

extern "C" void kernel_launch(void* const* d_in, const int* in_sizes, int n_in,
                              void* d_out, int out_size) {
    // Order-agnostic input resolution; never index d_in[i] for i >= n_in.
    int i_alpha = -1;
    for (int i = 0; i < n_in; i++) {
        if (in_sizes[i] == 1) { i_alpha = i; break; }
    }
    int big[2] = {-1, -1};
    int nb = 0;
    for (int i = 0; i < n_in && nb < 2; i++) {
        if (i != i_alpha) big[nb++] = i;
    }
    if (nb < 2) return;

    const int*   a     = (const int*)d_in[big[0]];     // int8 values in int32
    const int*   b     = (const int*)d_in[big[1]];
    const float* alpha = (i_alpha >= 0) ? (const float*)d_in[i_alpha] : nullptr;
    float*       out   = (float*)d_out;

    dim3 grid(N_DIM / 128, M_DIM / 128, 64);   // (n tiles, m tiles, batch)
    dim3 block(256);
    bmm_s8_imma_kernel<<<grid, block>>>(a, b, alpha, out);
}